// round 4
// baseline (speedup 1.0000x reference)
#include <cuda_runtime.h>
#include <cstdint>

// ============================================================================
// C[8192,4096] = X[8192,4096] @ W[4096,4096], fp32 in/out, tf32 mma.sync path
// (plain sm_100 target: no tcgen05 / no WGMMA / no TMA — cp.async + ldmatrix)
// ============================================================================
#define M_DIM 8192
#define K_DIM 4096
#define N_DIM 4096

#define BM 128
#define BN 256
#define BK 32                         // 32 floats = 128 B rows (swizzle unit 16B)
#define STAGES 4
#define ITERS (K_DIM / BK)            // 128
#define NT (N_DIM / BN)               // 16
#define MT (M_DIM / BM)               // 64
#define THREADS 512

#define A_BYTES (BM * BK * 4)         // 16384
#define B_BYTES (BN * BK * 4)         // 32768
#define STAGE_BYTES (A_BYTES + B_BYTES)   // 49152
#define SMEM_TOTAL (STAGES * STAGE_BYTES) // 196608

// 64 MB scratch: Bt[n][k] = W[k][n]  (K-major B for ldmatrix-friendly frags)
__device__ float g_Bt[(size_t)N_DIM * K_DIM];

// ============================================================================
// PTX helpers
// ============================================================================
__device__ __forceinline__ uint32_t smem_to_u32(const void* p) {
    uint32_t a;
    asm("{ .reg .u64 t; cvta.to.shared.u64 t, %1; cvt.u32.u64 %0, t; }"
        : "=r"(a) : "l"(p));
    return a;
}

#define CP_ASYNC16(smem_addr, gptr) \
    asm volatile("cp.async.cg.shared.global [%0], [%1], 16;" \
                 :: "r"(smem_addr), "l"(gptr) : "memory")
#define CP_COMMIT() asm volatile("cp.async.commit_group;" ::: "memory")
#define CP_WAIT(n)  asm volatile("cp.async.wait_group %0;" :: "n"(n) : "memory")

#define LDSM_X4(r0, r1, r2, r3, addr) \
    asm volatile("ldmatrix.sync.aligned.m8n8.x4.shared.b16 {%0,%1,%2,%3}, [%4];" \
                 : "=r"(r0), "=r"(r1), "=r"(r2), "=r"(r3) : "r"(addr))

// round-to-nearest tf32 (kills truncation bias; .b32 regs are valid f32 operands)
#define CVT_TF32(x) asm volatile("cvt.rna.tf32.f32 %0, %1;" : "=r"(x) : "r"(x))

#define MMA_TF32(c, a, b) \
    asm volatile( \
        "mma.sync.aligned.m16n8k8.row.col.f32.tf32.tf32.f32 " \
        "{%0,%1,%2,%3}, {%4,%5,%6,%7}, {%8,%9}, {%0,%1,%2,%3};" \
        : "+f"((c)[0]), "+f"((c)[1]), "+f"((c)[2]), "+f"((c)[3]) \
        : "r"((a)[0]), "r"((a)[1]), "r"((a)[2]), "r"((a)[3]), \
          "r"((b)[0]), "r"((b)[1]))

// ============================================================================
// Kernel 1: transpose W[k][n] -> Bt[n][k]
// ============================================================================
__global__ void __launch_bounds__(256) transpose_kernel(
    const float* __restrict__ B, float* __restrict__ Bt)
{
    __shared__ float t[32][33];
    int bx = blockIdx.x * 32;   // n block
    int by = blockIdx.y * 32;   // k block
    int tx = threadIdx.x, ty = threadIdx.y;
    #pragma unroll
    for (int j = 0; j < 32; j += 8)
        t[ty + j][tx] = B[(size_t)(by + ty + j) * N_DIM + (bx + tx)];
    __syncthreads();
    #pragma unroll
    for (int j = 0; j < 32; j += 8)
        Bt[(size_t)(bx + ty + j) * K_DIM + (by + tx)] = t[tx][ty + j];
}

// ============================================================================
// Kernel 2: tf32 mma.sync GEMM, 4-stage cp.async pipeline
//   512 threads = 16 warps in 4(m) x 4(n); warp tile 32x64
// ============================================================================
__global__ void __launch_bounds__(THREADS, 1) gemm_tf32_kernel(
    const float* __restrict__ X,
    const float* __restrict__ Bt,
    float* __restrict__ C)
{
    extern __shared__ __align__(1024) char smem[];
    uint32_t sb = smem_to_u32(smem);

    int tid  = threadIdx.x;
    int wid  = tid >> 5;
    int lane = tid & 31;
    int bid  = blockIdx.x;
    int tn   = bid % NT;
    int tm   = bid / NT;

    int wm = wid & 3;              // m group 0..3
    int wn = wid >> 2;             // n group 0..3
    int warp_m0 = wm * 32;
    int warp_n0 = wn * 64;

    // ---- per-thread cp.async source/dest precompute ----
    // A: 1024 16B chunks/stage, 2 per thread. B: 2048 chunks, 4 per thread.
    uint32_t offA[2]; const float* pA[2];
    #pragma unroll
    for (int p = 0; p < 2; p++) {
        int ca = tid + p * THREADS;
        int row = ca >> 3, c = ca & 7;
        offA[p] = row * 128 + ((c ^ (row & 7)) << 4);
        pA[p] = X + (size_t)(tm * BM + row) * K_DIM + c * 4;
    }
    uint32_t offB[4]; const float* pB[4];
    #pragma unroll
    for (int p = 0; p < 4; p++) {
        int cb = tid + p * THREADS;
        int row = cb >> 3, c = cb & 7;
        offB[p] = row * 128 + ((c ^ (row & 7)) << 4);
        pB[p] = Bt + (size_t)(tn * BN + row) * K_DIM + c * 4;
    }

    // ---- ldmatrix per-lane address components ----
    uint32_t a_rel = (uint32_t)(warp_m0 + (lane & 15)) * 128;  // within A stage
    uint32_t a_sw  = lane & 7;
    uint32_t a_co  = lane >> 4;                                 // 16B half of k8
    uint32_t b_rel = (uint32_t)(warp_n0 + (lane & 7) + ((lane >> 4) << 3)) * 128;
    uint32_t b_sw  = lane & 7;
    uint32_t b_ch  = (lane >> 3) & 1;

    float acc[2][8][4];
    #pragma unroll
    for (int mt = 0; mt < 2; mt++)
        #pragma unroll
        for (int nt = 0; nt < 8; nt++)
            #pragma unroll
            for (int v = 0; v < 4; v++) acc[mt][nt][v] = 0.0f;

    // ---- prologue: fill 3 stages ----
    #pragma unroll
    for (int i = 0; i < STAGES - 1; i++) {
        uint32_t sA = sb + i * STAGE_BYTES;
        uint32_t sB = sA + A_BYTES;
        #pragma unroll
        for (int p = 0; p < 2; p++) { CP_ASYNC16(sA + offA[p], pA[p]); pA[p] += BK; }
        #pragma unroll
        for (int p = 0; p < 4; p++) { CP_ASYNC16(sB + offB[p], pB[p]); pB[p] += BK; }
        CP_COMMIT();
    }

    // ---- main loop ----
    #pragma unroll 1
    for (int i = 0; i < ITERS; i++) {
        CP_WAIT(STAGES - 2);
        __syncthreads();

        // issue stage i+3 (slot just freed by iter i-1's compute)
        if (i + STAGES - 1 < ITERS) {
            int s = (i + STAGES - 1) & (STAGES - 1);
            uint32_t sA = sb + s * STAGE_BYTES;
            uint32_t sB = sA + A_BYTES;
            #pragma unroll
            for (int p = 0; p < 2; p++) { CP_ASYNC16(sA + offA[p], pA[p]); pA[p] += BK; }
            #pragma unroll
            for (int p = 0; p < 4; p++) { CP_ASYNC16(sB + offB[p], pB[p]); pB[p] += BK; }
        }
        CP_COMMIT();

        // compute stage i
        int s = i & (STAGES - 1);
        uint32_t As = sb + s * STAGE_BYTES;
        uint32_t Bs = As + A_BYTES;
        uint32_t aBase = As + a_rel;
        uint32_t bBase = Bs + b_rel;

        #pragma unroll
        for (int ks = 0; ks < 4; ks++) {
            uint32_t a[2][4];
            #pragma unroll
            for (int mt = 0; mt < 2; mt++) {
                uint32_t addr = aBase + mt * 2048 +
                                ((((uint32_t)ks * 2 + a_co) ^ a_sw) << 4);
                LDSM_X4(a[mt][0], a[mt][1], a[mt][2], a[mt][3], addr);
            }
            uint32_t b[8][2];
            #pragma unroll
            for (int j = 0; j < 4; j++) {
                uint32_t addr = bBase + j * 2048 +
                                ((((uint32_t)ks * 2 + b_ch) ^ b_sw) << 4);
                uint32_t r0, r1, r2, r3;
                LDSM_X4(r0, r1, r2, r3, addr);
                b[2 * j][0] = r0;  b[2 * j][1] = r1;
                b[2 * j + 1][0] = r2;  b[2 * j + 1][1] = r3;
            }
            // round fragments to tf32 (FMA pipe; overlaps tensor pipe)
            #pragma unroll
            for (int mt = 0; mt < 2; mt++)
                #pragma unroll
                for (int v = 0; v < 4; v++) CVT_TF32(a[mt][v]);
            #pragma unroll
            for (int nt = 0; nt < 8; nt++) {
                CVT_TF32(b[nt][0]); CVT_TF32(b[nt][1]);
            }
            #pragma unroll
            for (int mt = 0; mt < 2; mt++)
                #pragma unroll
                for (int nt = 0; nt < 8; nt++)
                    MMA_TF32(acc[mt][nt], a[mt], b[nt]);
        }
    }

    // ---- epilogue: direct global stores (float2) ----
    int row0 = tm * BM + warp_m0 + (lane >> 2);
    int col0 = tn * BN + warp_n0 + (lane & 3) * 2;
    #pragma unroll
    for (int mt = 0; mt < 2; mt++) {
        #pragma unroll
        for (int nt = 0; nt < 8; nt++) {
            int r = row0 + mt * 16;
            int c = col0 + nt * 8;
            float2* d0 = (float2*)(C + (size_t)r * N_DIM + c);
            float2* d1 = (float2*)(C + (size_t)(r + 8) * N_DIM + c);
            *d0 = make_float2(acc[mt][nt][0], acc[mt][nt][1]);
            *d1 = make_float2(acc[mt][nt][2], acc[mt][nt][3]);
        }
    }
}

// ============================================================================
// Host launcher
// ============================================================================
extern "C" void kernel_launch(void* const* d_in, const int* in_sizes, int n_in,
                              void* d_out, int out_size)
{
    const float* X = (const float*)d_in[0];   // [8192, 4096]
    const float* W = (const float*)d_in[1];   // [4096, 4096]
    float* C = (float*)d_out;                 // [8192, 4096]

    void* bt_ptr = nullptr;
    cudaGetSymbolAddress(&bt_ptr, g_Bt);

    dim3 tb(32, 8), tg(N_DIM / 32, K_DIM / 32);
    transpose_kernel<<<tg, tb>>>(W, (float*)bt_ptr);

    cudaFuncSetAttribute(gemm_tf32_kernel,
                         cudaFuncAttributeMaxDynamicSharedMemorySize, SMEM_TOTAL);
    gemm_tf32_kernel<<<MT * NT, THREADS, SMEM_TOTAL>>>(X, (const float*)bt_ptr, C);
}

// round 5
// speedup vs baseline: 1.1691x; 1.1691x over previous
#include <cuda_runtime.h>
#include <cstdint>

// ============================================================================
// C[8192,4096] = X[8192,4096] @ W[4096,4096], fp32 in/out, tf32 mma.sync path
// R5: pre-round both operands to tf32 (rna) in preprocessing; mainloop has
//     ZERO cvt instructions -> tensor issue density up.
// ============================================================================
#define M_DIM 8192
#define K_DIM 4096
#define N_DIM 4096

#define BM 128
#define BN 256
#define BK 32                         // 32 floats = 128 B rows (swizzle unit 16B)
#define STAGES 4
#define ITERS (K_DIM / BK)            // 128
#define NT (N_DIM / BN)               // 16
#define MT (M_DIM / BM)               // 64
#define THREADS 512

#define A_BYTES (BM * BK * 4)         // 16384
#define B_BYTES (BN * BK * 4)         // 32768
#define STAGE_BYTES (A_BYTES + B_BYTES)   // 49152
#define SMEM_TOTAL (STAGES * STAGE_BYTES) // 196608

// Scratch: Bt[n][k] = round_tf32(W[k][n]); Xr = round_tf32(X)
__device__ float g_Bt[(size_t)N_DIM * K_DIM];   // 64 MB
__device__ float g_Xr[(size_t)M_DIM * K_DIM];   // 128 MB

// ============================================================================
// PTX helpers
// ============================================================================
__device__ __forceinline__ uint32_t smem_to_u32(const void* p) {
    uint32_t a;
    asm("{ .reg .u64 t; cvta.to.shared.u64 t, %1; cvt.u32.u64 %0, t; }"
        : "=r"(a) : "l"(p));
    return a;
}

#define CP_ASYNC16(smem_addr, gptr) \
    asm volatile("cp.async.cg.shared.global [%0], [%1], 16;" \
                 :: "r"(smem_addr), "l"(gptr) : "memory")
#define CP_COMMIT() asm volatile("cp.async.commit_group;" ::: "memory")
#define CP_WAIT(n)  asm volatile("cp.async.wait_group %0;" :: "n"(n) : "memory")

#define LDSM_X4(r0, r1, r2, r3, addr) \
    asm volatile("ldmatrix.sync.aligned.m8n8.x4.shared.b16 {%0,%1,%2,%3}, [%4];" \
                 : "=r"(r0), "=r"(r1), "=r"(r2), "=r"(r3) : "r"(addr))

__device__ __forceinline__ float round_tf32(float x) {
    uint32_t u = __float_as_uint(x);
    asm("cvt.rna.tf32.f32 %0, %1;" : "=r"(u) : "r"(u));
    return __uint_as_float(u);
}

#define MMA_TF32(c, a, b) \
    asm volatile( \
        "mma.sync.aligned.m16n8k8.row.col.f32.tf32.tf32.f32 " \
        "{%0,%1,%2,%3}, {%4,%5,%6,%7}, {%8,%9}, {%0,%1,%2,%3};" \
        : "+f"((c)[0]), "+f"((c)[1]), "+f"((c)[2]), "+f"((c)[3]) \
        : "r"((a)[0]), "r"((a)[1]), "r"((a)[2]), "r"((a)[3]), \
          "r"((b)[0]), "r"((b)[1]))

// ============================================================================
// Kernel 0: round X -> Xr (elementwise tf32-rna), float4 vectorized
// ============================================================================
__global__ void __launch_bounds__(256) round_x_kernel(
    const float4* __restrict__ X, float4* __restrict__ Xr)
{
    size_t i = (size_t)blockIdx.x * 256 + threadIdx.x;
    float4 v = X[i];
    v.x = round_tf32(v.x); v.y = round_tf32(v.y);
    v.z = round_tf32(v.z); v.w = round_tf32(v.w);
    Xr[i] = v;
}

// ============================================================================
// Kernel 1: transpose + round W[k][n] -> Bt[n][k]
// ============================================================================
__global__ void __launch_bounds__(256) transpose_kernel(
    const float* __restrict__ B, float* __restrict__ Bt)
{
    __shared__ float t[32][33];
    int bx = blockIdx.x * 32;   // n block
    int by = blockIdx.y * 32;   // k block
    int tx = threadIdx.x, ty = threadIdx.y;
    #pragma unroll
    for (int j = 0; j < 32; j += 8)
        t[ty + j][tx] = round_tf32(B[(size_t)(by + ty + j) * N_DIM + (bx + tx)]);
    __syncthreads();
    #pragma unroll
    for (int j = 0; j < 32; j += 8)
        Bt[(size_t)(bx + ty + j) * K_DIM + (by + tx)] = t[tx][ty + j];
}

// ============================================================================
// Kernel 2: tf32 mma.sync GEMM, 4-stage cp.async pipeline
//   512 threads = 16 warps in 4(m) x 4(n); warp tile 32x64
//   Operands already tf32-rounded: no cvt in the mainloop.
// ============================================================================
__global__ void __launch_bounds__(THREADS, 1) gemm_tf32_kernel(
    const float* __restrict__ X,
    const float* __restrict__ Bt,
    float* __restrict__ C)
{
    extern __shared__ __align__(1024) char smem[];
    uint32_t sb = smem_to_u32(smem);

    int tid  = threadIdx.x;
    int wid  = tid >> 5;
    int lane = tid & 31;
    int bid  = blockIdx.x;
    int tn   = bid % NT;
    int tm   = bid / NT;

    int wm = wid & 3;              // m group 0..3
    int wn = wid >> 2;             // n group 0..3
    int warp_m0 = wm * 32;
    int warp_n0 = wn * 64;

    // ---- per-thread cp.async source/dest precompute ----
    uint32_t offA[2]; const float* pA[2];
    #pragma unroll
    for (int p = 0; p < 2; p++) {
        int ca = tid + p * THREADS;
        int row = ca >> 3, c = ca & 7;
        offA[p] = row * 128 + ((c ^ (row & 7)) << 4);
        pA[p] = X + (size_t)(tm * BM + row) * K_DIM + c * 4;
    }
    uint32_t offB[4]; const float* pB[4];
    #pragma unroll
    for (int p = 0; p < 4; p++) {
        int cb = tid + p * THREADS;
        int row = cb >> 3, c = cb & 7;
        offB[p] = row * 128 + ((c ^ (row & 7)) << 4);
        pB[p] = Bt + (size_t)(tn * BN + row) * K_DIM + c * 4;
    }

    // ---- ldmatrix per-lane address components ----
    uint32_t a_rel = (uint32_t)(warp_m0 + (lane & 15)) * 128;
    uint32_t a_sw  = lane & 7;
    uint32_t a_co  = lane >> 4;
    uint32_t b_rel = (uint32_t)(warp_n0 + (lane & 7) + ((lane >> 4) << 3)) * 128;
    uint32_t b_sw  = lane & 7;
    uint32_t b_ch  = (lane >> 3) & 1;

    float acc[2][8][4];
    #pragma unroll
    for (int mt = 0; mt < 2; mt++)
        #pragma unroll
        for (int nt = 0; nt < 8; nt++)
            #pragma unroll
            for (int v = 0; v < 4; v++) acc[mt][nt][v] = 0.0f;

    // ---- prologue: fill 3 stages ----
    #pragma unroll
    for (int i = 0; i < STAGES - 1; i++) {
        uint32_t sA = sb + i * STAGE_BYTES;
        uint32_t sB = sA + A_BYTES;
        #pragma unroll
        for (int p = 0; p < 2; p++) { CP_ASYNC16(sA + offA[p], pA[p]); pA[p] += BK; }
        #pragma unroll
        for (int p = 0; p < 4; p++) { CP_ASYNC16(sB + offB[p], pB[p]); pB[p] += BK; }
        CP_COMMIT();
    }

    // ---- main loop ----
    #pragma unroll 1
    for (int i = 0; i < ITERS; i++) {
        CP_WAIT(STAGES - 2);
        __syncthreads();

        if (i + STAGES - 1 < ITERS) {
            int s = (i + STAGES - 1) & (STAGES - 1);
            uint32_t sA = sb + s * STAGE_BYTES;
            uint32_t sB = sA + A_BYTES;
            #pragma unroll
            for (int p = 0; p < 2; p++) { CP_ASYNC16(sA + offA[p], pA[p]); pA[p] += BK; }
            #pragma unroll
            for (int p = 0; p < 4; p++) { CP_ASYNC16(sB + offB[p], pB[p]); pB[p] += BK; }
        }
        CP_COMMIT();

        int s = i & (STAGES - 1);
        uint32_t As = sb + s * STAGE_BYTES;
        uint32_t Bs = As + A_BYTES;
        uint32_t aBase = As + a_rel;
        uint32_t bBase = Bs + b_rel;

        #pragma unroll
        for (int ks = 0; ks < 4; ks++) {
            uint32_t a[2][4];
            #pragma unroll
            for (int mt = 0; mt < 2; mt++) {
                uint32_t addr = aBase + mt * 2048 +
                                ((((uint32_t)ks * 2 + a_co) ^ a_sw) << 4);
                LDSM_X4(a[mt][0], a[mt][1], a[mt][2], a[mt][3], addr);
            }
            uint32_t b[8][2];
            #pragma unroll
            for (int j = 0; j < 4; j++) {
                uint32_t addr = bBase + j * 2048 +
                                ((((uint32_t)ks * 2 + b_ch) ^ b_sw) << 4);
                uint32_t r0, r1, r2, r3;
                LDSM_X4(r0, r1, r2, r3, addr);
                b[2 * j][0] = r0;  b[2 * j][1] = r1;
                b[2 * j + 1][0] = r2;  b[2 * j + 1][1] = r3;
            }
            #pragma unroll
            for (int mt = 0; mt < 2; mt++)
                #pragma unroll
                for (int nt = 0; nt < 8; nt++)
                    MMA_TF32(acc[mt][nt], a[mt], b[nt]);
        }
    }

    // ---- epilogue: direct global stores (float2) ----
    int row0 = tm * BM + warp_m0 + (lane >> 2);
    int col0 = tn * BN + warp_n0 + (lane & 3) * 2;
    #pragma unroll
    for (int mt = 0; mt < 2; mt++) {
        #pragma unroll
        for (int nt = 0; nt < 8; nt++) {
            int r = row0 + mt * 16;
            int c = col0 + nt * 8;
            float2* d0 = (float2*)(C + (size_t)r * N_DIM + c);
            float2* d1 = (float2*)(C + (size_t)(r + 8) * N_DIM + c);
            *d0 = make_float2(acc[mt][nt][0], acc[mt][nt][1]);
            *d1 = make_float2(acc[mt][nt][2], acc[mt][nt][3]);
        }
    }
}

// ============================================================================
// Host launcher
// ============================================================================
extern "C" void kernel_launch(void* const* d_in, const int* in_sizes, int n_in,
                              void* d_out, int out_size)
{
    const float* X = (const float*)d_in[0];   // [8192, 4096]
    const float* W = (const float*)d_in[1];   // [4096, 4096]
    float* C = (float*)d_out;                 // [8192, 4096]

    void* bt_ptr = nullptr;
    cudaGetSymbolAddress(&bt_ptr, g_Bt);
    void* xr_ptr = nullptr;
    cudaGetSymbolAddress(&xr_ptr, g_Xr);

    // 0) round X -> Xr
    size_t n4 = (size_t)M_DIM * K_DIM / 4;
    round_x_kernel<<<(unsigned)(n4 / 256), 256>>>((const float4*)X, (float4*)xr_ptr);

    // 1) transpose + round W -> Bt
    dim3 tb(32, 8), tg(N_DIM / 32, K_DIM / 32);
    transpose_kernel<<<tg, tb>>>(W, (float*)bt_ptr);

    // 2) GEMM on pre-rounded operands
    cudaFuncSetAttribute(gemm_tf32_kernel,
                         cudaFuncAttributeMaxDynamicSharedMemorySize, SMEM_TOTAL);
    gemm_tf32_kernel<<<MT * NT, THREADS, SMEM_TOTAL>>>(
        (const float*)xr_ptr, (const float*)bt_ptr, C);
}

// round 6
// speedup vs baseline: 1.2656x; 1.0826x over previous
#include <cuda_runtime.h>
#include <cstdint>

// ============================================================================
// C[8192,4096] = X[8192,4096] @ W[4096,4096], fp32 in/out, tf32 mma.sync.
// R6: 2 CTAs/SM (BM=128, BN=128, BK=32, 3 stages, 96KB smem, 256 thr) so the
//     per-iter __syncthreads/wait_group bubbles of one CTA are hidden by the
//     other. Operands pre-rounded to tf32 (numerics unchanged).
// ============================================================================
#define M_DIM 8192
#define K_DIM 4096
#define N_DIM 4096

#define BM 128
#define BN 128
#define BK 32                         // 32 floats = 128 B rows
#define STAGES 3
#define ITERS (K_DIM / BK)            // 128
#define NT (N_DIM / BN)               // 32
#define MT (M_DIM / BM)               // 64
#define THREADS 256

#define A_BYTES (BM * BK * 4)         // 16384
#define B_BYTES (BN * BK * 4)         // 16384
#define STAGE_BYTES (A_BYTES + B_BYTES)   // 32768
#define SMEM_TOTAL (STAGES * STAGE_BYTES) // 98304

// Scratch: Bt[n][k] = round_tf32(W[k][n]); Xr = round_tf32(X)
__device__ float g_Bt[(size_t)N_DIM * K_DIM];   // 64 MB
__device__ float g_Xr[(size_t)M_DIM * K_DIM];   // 128 MB

// ============================================================================
// PTX helpers
// ============================================================================
__device__ __forceinline__ uint32_t smem_to_u32(const void* p) {
    uint32_t a;
    asm("{ .reg .u64 t; cvta.to.shared.u64 t, %1; cvt.u32.u64 %0, t; }"
        : "=r"(a) : "l"(p));
    return a;
}

#define CP_ASYNC16(smem_addr, gptr) \
    asm volatile("cp.async.cg.shared.global [%0], [%1], 16;" \
                 :: "r"(smem_addr), "l"(gptr) : "memory")
#define CP_COMMIT() asm volatile("cp.async.commit_group;" ::: "memory")
#define CP_WAIT(n)  asm volatile("cp.async.wait_group %0;" :: "n"(n) : "memory")

#define LDSM_X4(r0, r1, r2, r3, addr) \
    asm volatile("ldmatrix.sync.aligned.m8n8.x4.shared.b16 {%0,%1,%2,%3}, [%4];" \
                 : "=r"(r0), "=r"(r1), "=r"(r2), "=r"(r3) : "r"(addr))

__device__ __forceinline__ float round_tf32(float x) {
    uint32_t u = __float_as_uint(x);
    asm("cvt.rna.tf32.f32 %0, %1;" : "=r"(u) : "r"(u));
    return __uint_as_float(u);
}

#define MMA_TF32(c, a, b) \
    asm volatile( \
        "mma.sync.aligned.m16n8k8.row.col.f32.tf32.tf32.f32 " \
        "{%0,%1,%2,%3}, {%4,%5,%6,%7}, {%8,%9}, {%0,%1,%2,%3};" \
        : "+f"((c)[0]), "+f"((c)[1]), "+f"((c)[2]), "+f"((c)[3]) \
        : "r"((a)[0]), "r"((a)[1]), "r"((a)[2]), "r"((a)[3]), \
          "r"((b)[0]), "r"((b)[1]))

// ============================================================================
// Kernel 0: round X -> Xr (elementwise tf32-rna), float4 vectorized
// ============================================================================
__global__ void __launch_bounds__(256) round_x_kernel(
    const float4* __restrict__ X, float4* __restrict__ Xr)
{
    size_t i = (size_t)blockIdx.x * 256 + threadIdx.x;
    float4 v = X[i];
    v.x = round_tf32(v.x); v.y = round_tf32(v.y);
    v.z = round_tf32(v.z); v.w = round_tf32(v.w);
    Xr[i] = v;
}

// ============================================================================
// Kernel 1: transpose + round W[k][n] -> Bt[n][k]
// ============================================================================
__global__ void __launch_bounds__(256) transpose_kernel(
    const float* __restrict__ B, float* __restrict__ Bt)
{
    __shared__ float t[32][33];
    int bx = blockIdx.x * 32;   // n block
    int by = blockIdx.y * 32;   // k block
    int tx = threadIdx.x, ty = threadIdx.y;
    #pragma unroll
    for (int j = 0; j < 32; j += 8)
        t[ty + j][tx] = round_tf32(B[(size_t)(by + ty + j) * N_DIM + (bx + tx)]);
    __syncthreads();
    #pragma unroll
    for (int j = 0; j < 32; j += 8)
        Bt[(size_t)(bx + ty + j) * K_DIM + (by + tx)] = t[tx][ty + j];
}

// ============================================================================
// Kernel 2: tf32 mma.sync GEMM, 3-stage cp.async pipeline, 2 CTAs/SM
//   256 threads = 8 warps in 4(m) x 2(n); warp tile 32x64
// ============================================================================
__global__ void __launch_bounds__(THREADS, 2) gemm_tf32_kernel(
    const float* __restrict__ X,
    const float* __restrict__ Bt,
    float* __restrict__ C)
{
    extern __shared__ __align__(1024) char smem[];
    uint32_t sb = smem_to_u32(smem);

    int tid  = threadIdx.x;
    int wid  = tid >> 5;
    int lane = tid & 31;
    int bid  = blockIdx.x;
    int tn   = bid % NT;
    int tm   = bid / NT;

    int wm = wid & 3;              // m group 0..3
    int wn = wid >> 2;             // n group 0..1
    int warp_m0 = wm * 32;
    int warp_n0 = wn * 64;

    // ---- per-thread cp.async precompute ----
    // A: 1024 16B chunks/stage, 4 per thread. B: 1024 chunks, 4 per thread.
    uint32_t offA[4]; const float* pA[4];
    uint32_t offB[4]; const float* pB[4];
    #pragma unroll
    for (int p = 0; p < 4; p++) {
        int ca = tid + p * THREADS;
        int row = ca >> 3, c = ca & 7;
        uint32_t off = row * 128 + ((c ^ (row & 7)) << 4);
        offA[p] = off;
        offB[p] = off;
        pA[p] = X  + (size_t)(tm * BM + row) * K_DIM + c * 4;
        pB[p] = Bt + (size_t)(tn * BN + row) * K_DIM + c * 4;
    }

    // ---- ldmatrix per-lane address components ----
    uint32_t a_rel = (uint32_t)(warp_m0 + (lane & 15)) * 128;
    uint32_t a_sw  = lane & 7;
    uint32_t a_co  = lane >> 4;
    uint32_t b_rel = (uint32_t)(warp_n0 + (lane & 7) + ((lane >> 4) << 3)) * 128;
    uint32_t b_sw  = lane & 7;
    uint32_t b_ch  = (lane >> 3) & 1;

    float acc[2][8][4];
    #pragma unroll
    for (int mt = 0; mt < 2; mt++)
        #pragma unroll
        for (int nt = 0; nt < 8; nt++)
            #pragma unroll
            for (int v = 0; v < 4; v++) acc[mt][nt][v] = 0.0f;

    // ---- prologue: fill 2 stages ----
    #pragma unroll
    for (int i = 0; i < STAGES - 1; i++) {
        uint32_t sA = sb + i * STAGE_BYTES;
        uint32_t sB = sA + A_BYTES;
        #pragma unroll
        for (int p = 0; p < 4; p++) { CP_ASYNC16(sA + offA[p], pA[p]); pA[p] += BK; }
        #pragma unroll
        for (int p = 0; p < 4; p++) { CP_ASYNC16(sB + offB[p], pB[p]); pB[p] += BK; }
        CP_COMMIT();
    }

    // stage slot counters (mod 3, no division)
    int s_comp = 0;              // stage to compute this iter
    int s_load = STAGES - 1;     // stage slot to fill this iter

    // ---- main loop ----
    #pragma unroll 1
    for (int i = 0; i < ITERS; i++) {
        CP_WAIT(STAGES - 2);
        __syncthreads();

        if (i + STAGES - 1 < ITERS) {
            uint32_t sA = sb + s_load * STAGE_BYTES;
            uint32_t sB = sA + A_BYTES;
            #pragma unroll
            for (int p = 0; p < 4; p++) { CP_ASYNC16(sA + offA[p], pA[p]); pA[p] += BK; }
            #pragma unroll
            for (int p = 0; p < 4; p++) { CP_ASYNC16(sB + offB[p], pB[p]); pB[p] += BK; }
        }
        CP_COMMIT();

        uint32_t As = sb + s_comp * STAGE_BYTES;
        uint32_t Bs = As + A_BYTES;
        uint32_t aBase = As + a_rel;
        uint32_t bBase = Bs + b_rel;

        #pragma unroll
        for (int ks = 0; ks < 4; ks++) {
            uint32_t a[2][4];
            #pragma unroll
            for (int mt = 0; mt < 2; mt++) {
                uint32_t addr = aBase + mt * 2048 +
                                ((((uint32_t)ks * 2 + a_co) ^ a_sw) << 4);
                LDSM_X4(a[mt][0], a[mt][1], a[mt][2], a[mt][3], addr);
            }
            uint32_t b[8][2];
            #pragma unroll
            for (int j = 0; j < 4; j++) {
                uint32_t addr = bBase + j * 2048 +
                                ((((uint32_t)ks * 2 + b_ch) ^ b_sw) << 4);
                uint32_t r0, r1, r2, r3;
                LDSM_X4(r0, r1, r2, r3, addr);
                b[2 * j][0] = r0;  b[2 * j][1] = r1;
                b[2 * j + 1][0] = r2;  b[2 * j + 1][1] = r3;
            }
            #pragma unroll
            for (int mt = 0; mt < 2; mt++)
                #pragma unroll
                for (int nt = 0; nt < 8; nt++)
                    MMA_TF32(acc[mt][nt], a[mt], b[nt]);
        }

        if (++s_comp == STAGES) s_comp = 0;
        if (++s_load == STAGES) s_load = 0;
    }

    // ---- epilogue: direct global stores (float2) ----
    int row0 = tm * BM + warp_m0 + (lane >> 2);
    int col0 = tn * BN + warp_n0 + (lane & 3) * 2;
    #pragma unroll
    for (int mt = 0; mt < 2; mt++) {
        #pragma unroll
        for (int nt = 0; nt < 8; nt++) {
            int r = row0 + mt * 16;
            int c = col0 + nt * 8;
            float2* d0 = (float2*)(C + (size_t)r * N_DIM + c);
            float2* d1 = (float2*)(C + (size_t)(r + 8) * N_DIM + c);
            *d0 = make_float2(acc[mt][nt][0], acc[mt][nt][1]);
            *d1 = make_float2(acc[mt][nt][2], acc[mt][nt][3]);
        }
    }
}

// ============================================================================
// Host launcher
// ============================================================================
extern "C" void kernel_launch(void* const* d_in, const int* in_sizes, int n_in,
                              void* d_out, int out_size)
{
    const float* X = (const float*)d_in[0];   // [8192, 4096]
    const float* W = (const float*)d_in[1];   // [4096, 4096]
    float* C = (float*)d_out;                 // [8192, 4096]

    void* bt_ptr = nullptr;
    cudaGetSymbolAddress(&bt_ptr, g_Bt);
    void* xr_ptr = nullptr;
    cudaGetSymbolAddress(&xr_ptr, g_Xr);

    // 0) round X -> Xr
    size_t n4 = (size_t)M_DIM * K_DIM / 4;
    round_x_kernel<<<(unsigned)(n4 / 256), 256>>>((const float4*)X, (float4*)xr_ptr);

    // 1) transpose + round W -> Bt
    dim3 tb(32, 8), tg(N_DIM / 32, K_DIM / 32);
    transpose_kernel<<<tg, tb>>>(W, (float*)bt_ptr);

    // 2) GEMM on pre-rounded operands, 2 CTAs/SM
    cudaFuncSetAttribute(gemm_tf32_kernel,
                         cudaFuncAttributeMaxDynamicSharedMemorySize, SMEM_TOTAL);
    gemm_tf32_kernel<<<MT * NT, THREADS, SMEM_TOTAL>>>(
        (const float*)xr_ptr, (const float*)bt_ptr, C);
}